// round 2
// baseline (speedup 1.0000x reference)
#include <cuda_runtime.h>
#include <cstddef>

// Problem constants
#define B_  8
#define T_  2048
#define D_  256
#define DK_ 64
#define NHEAD_ 4

// Fused attention kernel tiling
#define R_   16      // query rows per CTA
#define ST_  128     // key/value tile along s
#define TH_  256     // threads per CTA

// Scratch for projected q/k/v  (8*2048*64 fp32 = 4 MB each)
__device__ float g_qs[B_ * T_ * DK_];
__device__ float g_ks[B_ * T_ * DK_];
__device__ float g_vs[B_ * T_ * DK_];

// ---------------------------------------------------------------------------
// Kernel 1: projections  qs = q@Wq, ks = k@Wk, vs = v@Wv
// grid = (512, 3), block = 256.  Each block: 32 rows x 64 cols of one proj.
// ---------------------------------------------------------------------------
__global__ void proj_kernel(const float* __restrict__ q,
                            const float* __restrict__ k,
                            const float* __restrict__ v,
                            const float* __restrict__ Wq,
                            const float* __restrict__ Wk,
                            const float* __restrict__ Wv) {
    __shared__ float xs[32 * 256];

    const float* x;
    const float* W;
    float* dst;
    if (blockIdx.y == 0)      { x = q; W = Wq; dst = g_qs; }
    else if (blockIdx.y == 1) { x = k; W = Wk; dst = g_ks; }
    else                      { x = v; W = Wv; dst = g_vs; }

    const int row0 = blockIdx.x * 32;
    const int tid  = threadIdx.x;

    // load 32 input rows (32*256 floats) as float4
    {
        const float4* src4 = reinterpret_cast<const float4*>(x + (size_t)row0 * D_);
        float4* xs4 = reinterpret_cast<float4*>(xs);
        #pragma unroll
        for (int i = tid; i < 32 * 256 / 4; i += TH_) xs4[i] = src4[i];
    }
    __syncthreads();

    // thread tile: 2 rows x 4 cols
    const int jg = tid & 15;          // 16 col groups
    const int rg = tid >> 4;          // 16 row groups
    const int j0 = jg * 4;
    const int r0 = rg * 2;

    float acc0[4] = {0.f, 0.f, 0.f, 0.f};
    float acc1[4] = {0.f, 0.f, 0.f, 0.f};

    for (int i = 0; i < D_; i += 4) {
        float4 xa = *reinterpret_cast<const float4*>(&xs[r0 * 256 + i]);
        float4 xb = *reinterpret_cast<const float4*>(&xs[(r0 + 1) * 256 + i]);
        const float xav[4] = {xa.x, xa.y, xa.z, xa.w};
        const float xbv[4] = {xb.x, xb.y, xb.z, xb.w};
        #pragma unroll
        for (int ii = 0; ii < 4; ii++) {
            float4 w = *reinterpret_cast<const float4*>(&W[(size_t)(i + ii) * DK_ + j0]);
            acc0[0] += xav[ii] * w.x; acc0[1] += xav[ii] * w.y;
            acc0[2] += xav[ii] * w.z; acc0[3] += xav[ii] * w.w;
            acc1[0] += xbv[ii] * w.x; acc1[1] += xbv[ii] * w.y;
            acc1[2] += xbv[ii] * w.z; acc1[3] += xbv[ii] * w.w;
        }
    }

    float4* o0 = reinterpret_cast<float4*>(&dst[(size_t)(row0 + r0) * DK_ + j0]);
    float4* o1 = reinterpret_cast<float4*>(&dst[(size_t)(row0 + r0 + 1) * DK_ + j0]);
    *o0 = make_float4(acc0[0], acc0[1], acc0[2], acc0[3]);
    *o1 = make_float4(acc1[0], acc1[1], acc1[2], acc1[3]);
}

// ---------------------------------------------------------------------------
// Kernel 2: fused  scores -> softmax -> write attn x4 -> attn@V -> @Wo
// grid = B * (T/R) = 1024 CTAs, block = 256 threads.
// Dynamic smem: scores[R*T] + kv[ST*65] + qh[R*DK] + rinv[R]
// ---------------------------------------------------------------------------
#define SMEM_FLOATS (R_ * T_ + ST_ * 65 + R_ * DK_ + R_)
#define SMEM_BYTES  (SMEM_FLOATS * 4)

__global__ void attn_kernel(const float* __restrict__ Wo,
                            float* __restrict__ out,
                            float* __restrict__ attn_out) {
    extern __shared__ float sm[];
    float* sc   = sm;                       // R*T   = 32768 floats (128 KB)
    float* kv   = sc + R_ * T_;             // 128*65 = 8320 floats
    float* qh   = kv + ST_ * 65;            // R*DK  = 1024 floats
    float* rinv = qh + R_ * DK_;            // R

    const int tid = threadIdx.x;
    const int b   = blockIdx.x >> 7;        // 128 row-tiles per batch
    const int t0  = (blockIdx.x & 127) * R_;

    // ---- load q tile into smem -------------------------------------------
    {
        const size_t qbase = ((size_t)b * T_ + t0) * DK_;
        for (int i = tid; i < R_ * DK_; i += TH_) qh[i] = g_qs[qbase + i];
    }
    __syncthreads();

    // ---- phase 1: scores = qs . ks^T * 0.125 ------------------------------
    {
        const int s_local = tid & 127;       // 128 s per tile
        const int rbase   = (tid >> 7) * 8;  // rows 0-7 or 8-15
        for (int st = 0; st < T_; st += ST_) {
            // load K tile with stride-65 padding (conflict-free lane-varies-s)
            const float* ksrc = g_ks + ((size_t)b * T_ + st) * DK_;
            for (int i = tid; i < ST_ * DK_; i += TH_) {
                int s = i >> 6, d = i & 63;
                kv[s * 65 + d] = ksrc[i];
            }
            __syncthreads();

            float acc[8] = {0.f, 0.f, 0.f, 0.f, 0.f, 0.f, 0.f, 0.f};
            #pragma unroll 4
            for (int d = 0; d < DK_; d += 4) {
                const float k0 = kv[s_local * 65 + d + 0];
                const float k1 = kv[s_local * 65 + d + 1];
                const float k2 = kv[s_local * 65 + d + 2];
                const float k3 = kv[s_local * 65 + d + 3];
                #pragma unroll
                for (int r = 0; r < 8; r++) {
                    float4 q4 = *reinterpret_cast<const float4*>(&qh[(rbase + r) * DK_ + d]);
                    acc[r] += q4.x * k0 + q4.y * k1 + q4.z * k2 + q4.w * k3;
                }
            }
            #pragma unroll
            for (int r = 0; r < 8; r++)
                sc[(rbase + r) * T_ + st + s_local] = acc[r] * 0.125f;
            __syncthreads();   // before kv reuse next iter
        }
    }

    // ---- phase 2: softmax (two-pass, per-row, 16 threads per row) ---------
    {
        const int r   = tid >> 4;
        const int l16 = tid & 15;
        float* row = sc + r * T_;

        float m = -1e30f;
        for (int s = l16; s < T_; s += 16) m = fmaxf(m, row[s]);
        #pragma unroll
        for (int o = 8; o > 0; o >>= 1)
            m = fmaxf(m, __shfl_xor_sync(0xffffffffu, m, o));

        float sum = 0.f;
        for (int s = l16; s < T_; s += 16) {
            float p = __expf(row[s] - m);
            row[s] = p;
            sum += p;
        }
        #pragma unroll
        for (int o = 8; o > 0; o >>= 1)
            sum += __shfl_xor_sync(0xffffffffu, sum, o);

        if (l16 == 0) rinv[r] = 1.0f / sum;
    }
    __syncthreads();

    // ---- phase 3: normalize in place + write attn to all 4 heads ----------
    {
        const size_t HTT   = (size_t)B_ * T_ * T_;           // 33,554,432
        const size_t abase = ((size_t)b * T_ + t0) * T_;
        float4* sc4 = reinterpret_cast<float4*>(sc);
        for (int i = tid; i < R_ * T_ / 4; i += TH_) {
            const int rr = i >> 9;                           // T/4 = 512 per row
            const int s4 = i & 511;
            const float inv = rinv[rr];
            float4 vv = sc4[i];
            vv.x *= inv; vv.y *= inv; vv.z *= inv; vv.w *= inv;
            sc4[i] = vv;
            const size_t off = abase + (size_t)rr * T_ + (size_t)s4 * 4;
            #pragma unroll
            for (int h = 0; h < NHEAD_; h++)
                *reinterpret_cast<float4*>(attn_out + (size_t)h * HTT + off) = vv;
        }
    }
    __syncthreads();

    // ---- phase 4: head = attn @ vs  (thread = 1 row x 4 cols) -------------
    float a0 = 0.f, a1 = 0.f, a2 = 0.f, a3 = 0.f;
    {
        const int d4 = (tid & 15) * 4;
        const int hr = tid >> 4;
        for (int st = 0; st < T_; st += ST_) {
            __syncthreads();   // kv reuse guard
            const float4* vsrc =
                reinterpret_cast<const float4*>(g_vs + ((size_t)b * T_ + st) * DK_);
            float4* kv4 = reinterpret_cast<float4*>(kv);
            for (int i = tid; i < ST_ * DK_ / 4; i += TH_) kv4[i] = vsrc[i];
            __syncthreads();

            const float* prow = sc + hr * T_ + st;
            #pragma unroll 8
            for (int sl = 0; sl < ST_; sl++) {
                const float p = prow[sl];
                float4 vv = *reinterpret_cast<const float4*>(&kv[sl * DK_ + d4]);
                a0 += p * vv.x; a1 += p * vv.y; a2 += p * vv.z; a3 += p * vv.w;
            }
        }
        __syncthreads();
        *reinterpret_cast<float4*>(&qh[hr * DK_ + d4]) = make_float4(a0, a1, a2, a3);
    }
    __syncthreads();

    // ---- phase 5: outputs = head @ Wo  (thread = column c, 16 rows) -------
    {
        const int c = tid;
        float o[R_];
        #pragma unroll
        for (int rr = 0; rr < R_; rr++) o[rr] = 0.f;

        for (int d = 0; d < DK_; d++) {
            const float w = Wo[(size_t)d * D_ + c];
            #pragma unroll
            for (int rr = 0; rr < R_; rr++) o[rr] += qh[rr * DK_ + d] * w;
        }
        const size_t obase = ((size_t)b * T_ + t0) * D_ + c;
        #pragma unroll
        for (int rr = 0; rr < R_; rr++) out[obase + (size_t)rr * D_] = o[rr];
    }
}

// ---------------------------------------------------------------------------
// launch
// ---------------------------------------------------------------------------
extern "C" void kernel_launch(void* const* d_in, const int* in_sizes, int n_in,
                              void* d_out, int out_size) {
    const float* q  = (const float*)d_in[0];
    const float* k  = (const float*)d_in[1];
    const float* v  = (const float*)d_in[2];
    const float* Wq = (const float*)d_in[3];
    const float* Wk = (const float*)d_in[4];
    const float* Wv = (const float*)d_in[5];
    const float* Wo = (const float*)d_in[6];

    float* out      = (float*)d_out;                               // [8,2048,256]
    float* attn_out = (float*)d_out + (size_t)B_ * T_ * D_;        // [4,8,2048,2048]

    // projections: 16384 rows / 32 per block = 512 blocks, y = {q,k,v}
    dim3 gp(512, 3, 1);
    proj_kernel<<<gp, TH_>>>(q, k, v, Wq, Wk, Wv);

    // fused attention
    cudaFuncSetAttribute(attn_kernel, cudaFuncAttributeMaxDynamicSharedMemorySize,
                         SMEM_BYTES);
    attn_kernel<<<B_ * (T_ / R_), TH_, SMEM_BYTES>>>(Wo, out, attn_out);
}